// round 1
// baseline (speedup 1.0000x reference)
#include <cuda_runtime.h>
#include <math.h>

#define NRAYS 16384
#define NSEG 8
#define PTS_PER_SEG 32
#define IMG_DIM 128

// -------- device scratch (no allocations allowed) --------
__device__ float g_acc[NSEG * NRAYS];
__device__ float g_prodv[NSEG * NRAYS];
__device__ float g_gray[NRAYS];
__device__ double g_sum, g_sumsq;
__device__ unsigned g_minkey, g_maxkey;

// -------- ordered-float key for atomicMin/Max --------
__device__ __forceinline__ unsigned fkey(float f) {
    unsigned u = __float_as_uint(f);
    return (u & 0x80000000u) ? ~u : (u | 0x80000000u);
}
__device__ __forceinline__ float funkey(unsigned k) {
    return (k & 0x80000000u) ? __uint_as_float(k & 0x7FFFFFFFu)
                             : __uint_as_float(~k);
}

__global__ void reset_kernel() {
    g_sum = 0.0;
    g_sumsq = 0.0;
    g_minkey = 0xFFFFFFFFu;
    g_maxkey = 0u;
}

// -------- trilinear sample of both volumes (zero padding outside) --------
__device__ __forceinline__ void tri_sample(const float* __restrict__ img,
                                           const float* __restrict__ opa,
                                           float fx, float fy, float fz,
                                           float& f, float& d) {
    float x0 = floorf(fx), y0 = floorf(fy), z0 = floorf(fz);
    int ix = (int)x0, iy = (int)y0, iz = (int)z0;
    float wx = fx - x0, wy = fy - y0, wz = fz - z0;
    f = 0.f;
    d = 0.f;
#pragma unroll
    for (int dz = 0; dz < 2; dz++) {
#pragma unroll
        for (int dy = 0; dy < 2; dy++) {
#pragma unroll
            for (int dx = 0; dx < 2; dx++) {
                int X = ix + dx, Y = iy + dy, Z = iz + dz;
                if ((unsigned)X < 128u && (unsigned)Y < 128u && (unsigned)Z < 128u) {
                    float wt = (dx ? wx : 1.f - wx) * (dy ? wy : 1.f - wy) *
                               (dz ? wz : 1.f - wz);
                    int idx = (Z << 14) + (Y << 7) + X;
                    f += wt * __ldg(img + idx);
                    d += wt * __ldg(opa + idx);
                }
            }
        }
    }
}

// -------- per-(ray,segment) rendering --------
// grid: (NSEG, 128 rows), block: 128 threads (one per pixel column w)
__global__ void __launch_bounds__(128)
render_kernel(const float* __restrict__ img, const float* __restrict__ opa,
              const float* __restrict__ Rm, const float* __restrict__ Tv) {
    int w = threadIdx.x;
    int seg = blockIdx.x;
    int h = blockIdx.y;

    // NDC grid: xs = linspace(1,-1,128) over w; ys likewise over h
    float gx = 1.f + (float)w * (-2.f / 127.f);
    float gy = 1.f + (float)h * (-2.f / 127.f);
    const float INV_FOCAL = 1.f / 1.7320508f;
    float dc0 = gx * INV_FOCAL, dc1 = gy * INV_FOCAL;  // dc2 = 1

    float R00 = Rm[0], R01 = Rm[1], R02 = Rm[2];
    float R10 = Rm[3], R11 = Rm[4], R12 = Rm[5];
    float R20 = Rm[6], R21 = Rm[7], R22 = Rm[8];
    float T0 = Tv[0], T1 = Tv[1], T2 = Tv[2];

    // dirs_world[j] = sum_i dirs_cam[i] * R[j][i]
    float dwx = dc0 * R00 + dc1 * R01 + R02;
    float dwy = dc0 * R10 + dc1 * R11 + R12;
    float dwz = dc0 * R20 + dc1 * R21 + R22;
    // origin[j] = sum_i (-T[i]) * R[j][i]
    float ox = -(T0 * R00 + T1 * R01 + T2 * R02);
    float oy = -(T0 * R10 + T1 * R11 + T2 * R12);
    float oz = -(T0 * R20 + T1 * R21 + T2 * R22);

    // sample coord: fx = ((pos/half_extent)+1)*0.5*127 = pos*s + 63.5
    const float HE = 1.48828125f;  // (3/128)*127/2
    const float s = 63.5f / HE;
    float ax = dwx * s, bx = ox * s + 63.5f;
    float ay = dwy * s, by = oy * s + 63.5f;
    float az = dwz * s, bz = oz * s + 63.5f;

    float Tt = 1.f, acc = 0.f;
    int p0 = seg * PTS_PER_SEG;

#pragma unroll
    for (int g = 0; g < PTS_PER_SEG / 4; g++) {
        float fv[4], dv[4];
#pragma unroll
        for (int k = 0; k < 4; k++) {
            int p = p0 + g * 4 + k;
            float depth = 2.f + (float)p * (4.f / 255.f);
            tri_sample(img, opa, ax * depth + bx, ay * depth + by,
                       az * depth + bz, fv[k], dv[k]);
            dv[k] *= 0.1f;  // densities = opacity * SCALING
        }
#pragma unroll
        for (int k = 0; k < 4; k++) {
            // (1.0 + 1e-10) == 1.0f in fp32 (matches JAX fp32 trace)
            acc += fv[k] * dv[k] * Tt;
            Tt *= (1.f - dv[k]);
        }
    }

    int r = h * 128 + w;
    g_acc[seg * NRAYS + r] = acc;
    g_prodv[seg * NRAYS + r] = Tt;
}

// -------- combine segments + global stats --------
__global__ void __launch_bounds__(256) combine_kernel() {
    int r = blockIdx.x * blockDim.x + threadIdx.x;  // 64 blocks x 256
    float gray = 0.f;
    float Tt = 1.f;
#pragma unroll
    for (int s2 = 0; s2 < NSEG; s2++) {
        gray += g_acc[s2 * NRAYS + r] * Tt;
        Tt *= g_prodv[s2 * NRAYS + r];
    }
    g_gray[r] = gray;

    // block reduction: sum, sumsq (double), min, max
    double sm = (double)gray;
    double sq = (double)gray * (double)gray;
    float mn = gray, mx = gray;
#pragma unroll
    for (int off = 16; off > 0; off >>= 1) {
        sm += __shfl_down_sync(0xFFFFFFFFu, sm, off);
        sq += __shfl_down_sync(0xFFFFFFFFu, sq, off);
        mn = fminf(mn, __shfl_down_sync(0xFFFFFFFFu, mn, off));
        mx = fmaxf(mx, __shfl_down_sync(0xFFFFFFFFu, mx, off));
    }
    __shared__ double s_sm[8], s_sq[8];
    __shared__ float s_mn[8], s_mx[8];
    int lane = threadIdx.x & 31, wid = threadIdx.x >> 5;
    if (lane == 0) {
        s_sm[wid] = sm;
        s_sq[wid] = sq;
        s_mn[wid] = mn;
        s_mx[wid] = mx;
    }
    __syncthreads();
    if (wid == 0) {
        sm = (lane < 8) ? s_sm[lane] : 0.0;
        sq = (lane < 8) ? s_sq[lane] : 0.0;
        mn = (lane < 8) ? s_mn[lane] : 3.0e38f;
        mx = (lane < 8) ? s_mx[lane] : -3.0e38f;
#pragma unroll
        for (int off = 4; off > 0; off >>= 1) {
            sm += __shfl_down_sync(0xFFFFFFFFu, sm, off);
            sq += __shfl_down_sync(0xFFFFFFFFu, sq, off);
            mn = fminf(mn, __shfl_down_sync(0xFFFFFFFFu, mn, off));
            mx = fmaxf(mx, __shfl_down_sync(0xFFFFFFFFu, mx, off));
        }
        if (lane == 0) {
            atomicAdd(&g_sum, sm);
            atomicAdd(&g_sumsq, sq);
            atomicMin(&g_minkey, fkey(mn));
            atomicMax(&g_maxkey, fkey(mx));
        }
    }
}

// -------- standardize + normalize, with transpose to [W,H] layout --------
__global__ void __launch_bounds__(256) finalize_kernel(float* __restrict__ out) {
    int o = blockIdx.x * blockDim.x + threadIdx.x;  // 64 blocks x 256
    double sum = g_sum, sumsq = g_sumsq;
    double mean = sum / 16384.0;
    double var = (sumsq - sum * sum / 16384.0) / 16383.0;
    float stddev = (float)sqrt(var > 0.0 ? var : 0.0);
    float gmin = funkey(g_minkey), gmax = funkey(g_maxkey);
    float fmean = (float)mean;
    float inv = 1.f / (stddev + 1e-8f);
    float stmin = (gmin - fmean) * inv;
    float stmax = (gmax - fmean) * inv;
    // out layout [1,1,W,H]: out[w*128+h] = gray(h,w)
    int w = o >> 7, h = o & 127;
    float st = (g_gray[h * 128 + w] - fmean) * inv;
    out[o] = (st - stmin + 1e-8f) / (stmax - stmin + 1e-8f);
}

extern "C" void kernel_launch(void* const* d_in, const int* in_sizes, int n_in,
                              void* d_out, int out_size) {
    const float* img = (const float*)d_in[0];  // image3d [1,1,128,128,128]
    const float* opa = (const float*)d_in[1];  // opacity  [1,1,128,128,128]
    const float* Rm = (const float*)d_in[2];   // R [1,3,3]
    const float* Tv = (const float*)d_in[3];   // T [1,3]
    float* out = (float*)d_out;                // [1,1,128,128]

    reset_kernel<<<1, 1>>>();
    render_kernel<<<dim3(NSEG, IMG_DIM), 128>>>(img, opa, Rm, Tv);
    combine_kernel<<<64, 256>>>();
    finalize_kernel<<<64, 256>>>(out);
}